// round 1
// baseline (speedup 1.0000x reference)
#include <cuda_runtime.h>

// PLIF scan: x [B=16, T=16, C=128, H=32, W=32] fp32, scalar leak w.
//   mem = w*mem + x_t; spike = (mem >= 1); mem *= (1 - spike)
// out = spikes, same shape/dtype as x.
//
// Layout: for fixed (b, spatial-index s in [0, CHW)), the T samples are at
// offset b*T*CHW + t*CHW + s. Each thread owns 4 consecutive neurons (one
// float4 lane) and walks all 16 timesteps. All 16 loads are address-independent
// of the scan -> front-batched LDG.128, MLP=16, fully coalesced.

#define B_   16
#define T_   16
#define CHW_ 131072            // 128*32*32
#define CHW4 (CHW_ / 4)        // 32768 float4 per (b,t) plane
#define NV4  (B_ * CHW4)       // 524288 threads total

__global__ __launch_bounds__(256) void plif_kernel(
    const float4* __restrict__ x,
    const float*  __restrict__ wp,
    float4*       __restrict__ out)
{
    const int tid = blockIdx.x * blockDim.x + threadIdx.x;
    if (tid >= NV4) return;

    const float w = *wp;                     // scalar, L1-broadcast

    const int b = tid >> 15;                 // tid / CHW4
    const int s = tid & (CHW4 - 1);          // tid % CHW4
    const float4* xb = x   + (size_t)b * (T_ * CHW4) + s;
    float4*       ob = out + (size_t)b * (T_ * CHW4) + s;

    // Front-batch all 16 loads (independent addresses -> deep MLP).
    float4 xs[T_];
    #pragma unroll
    for (int t = 0; t < T_; ++t)
        xs[t] = xb[t * CHW4];

    float m0 = 0.f, m1 = 0.f, m2 = 0.f, m3 = 0.f;

    #pragma unroll
    for (int t = 0; t < T_; ++t) {
        m0 = fmaf(w, m0, xs[t].x);
        m1 = fmaf(w, m1, xs[t].y);
        m2 = fmaf(w, m2, xs[t].z);
        m3 = fmaf(w, m3, xs[t].w);

        const float s0 = (m0 >= 1.0f) ? 1.0f : 0.0f;
        const float s1 = (m1 >= 1.0f) ? 1.0f : 0.0f;
        const float s2 = (m2 >= 1.0f) ? 1.0f : 0.0f;
        const float s3 = (m3 >= 1.0f) ? 1.0f : 0.0f;

        // mem *= (1 - spike)  ->  hard reset on spike
        m0 = (s0 != 0.0f) ? 0.0f : m0;
        m1 = (s1 != 0.0f) ? 0.0f : m1;
        m2 = (s2 != 0.0f) ? 0.0f : m2;
        m3 = (s3 != 0.0f) ? 0.0f : m3;

        float4 o; o.x = s0; o.y = s1; o.z = s2; o.w = s3;
        ob[t * CHW4] = o;
    }
}

extern "C" void kernel_launch(void* const* d_in, const int* in_sizes, int n_in,
                              void* d_out, int out_size)
{
    const float4* x  = (const float4*)d_in[0];
    const float*  wp = (const float*)d_in[1];
    float4* out = (float4*)d_out;

    const int threads = 256;
    const int blocks  = (NV4 + threads - 1) / threads;   // 2048
    plif_kernel<<<blocks, threads>>>(x, wp, out);
}

// round 2
// speedup vs baseline: 1.0082x; 1.0082x over previous
#include <cuda_runtime.h>

// PLIF scan: x [B=16, T=16, C=128, H=32, W=32] fp32, scalar leak w.
//   mem = w*mem + x_t; spike = (mem >= 1); mem *= (1 - spike)
// out = spikes, same shape/dtype as x.
//
// Round 2: single balanced wave. 524288 float4 lanes, 2 lanes per thread
// -> 262144 threads = 1024 CTAs of 256 (<= 7 CTAs/SM on 148 SMs => exactly
// one resident wave, no wave-transition tail). Streaming cache hints
// (__ldcs/__stcs) since every byte is touched exactly once.

#define B_    16
#define T_    16
#define CHW4  32768                  // (128*32*32)/4 float4 per (b,t) plane
#define NV4   (B_ * CHW4)            // 524288 float4 lanes
#define LPT   2                      // lanes per thread
#define NTHR  (NV4 / LPT)            // 262144
#define TPB   256
#define NBLK  (NTHR / TPB)           // 1024

__device__ __forceinline__ void plif_lane(const float4* __restrict__ x,
                                          float4* __restrict__ out,
                                          int lane, float w)
{
    const int b = lane >> 15;                 // lane / CHW4
    const int s = lane & (CHW4 - 1);          // lane % CHW4
    const float4* xb = x   + (size_t)b * (T_ * CHW4) + s;
    float4*       ob = out + (size_t)b * (T_ * CHW4) + s;

    // Front-batch loads (independent addresses -> deep MLP).
    float4 xs[T_];
    #pragma unroll
    for (int t = 0; t < T_; ++t)
        xs[t] = __ldcs(&xb[t * CHW4]);

    float m0 = 0.f, m1 = 0.f, m2 = 0.f, m3 = 0.f;

    #pragma unroll
    for (int t = 0; t < T_; ++t) {
        m0 = fmaf(w, m0, xs[t].x);
        m1 = fmaf(w, m1, xs[t].y);
        m2 = fmaf(w, m2, xs[t].z);
        m3 = fmaf(w, m3, xs[t].w);

        const float s0 = (m0 >= 1.0f) ? 1.0f : 0.0f;
        const float s1 = (m1 >= 1.0f) ? 1.0f : 0.0f;
        const float s2 = (m2 >= 1.0f) ? 1.0f : 0.0f;
        const float s3 = (m3 >= 1.0f) ? 1.0f : 0.0f;

        m0 = (s0 != 0.0f) ? 0.0f : m0;
        m1 = (s1 != 0.0f) ? 0.0f : m1;
        m2 = (s2 != 0.0f) ? 0.0f : m2;
        m3 = (s3 != 0.0f) ? 0.0f : m3;

        float4 o; o.x = s0; o.y = s1; o.z = s2; o.w = s3;
        __stcs(&ob[t * CHW4], o);
    }
}

__global__ __launch_bounds__(TPB) void plif_kernel(
    const float4* __restrict__ x,
    const float*  __restrict__ wp,
    float4*       __restrict__ out)
{
    const int tid = blockIdx.x * blockDim.x + threadIdx.x;
    const float w = *wp;                      // scalar, L1-broadcast

    // Lane 0: [0, NTHR), Lane 1: [NTHR, 2*NTHR) — both fully coalesced
    // across consecutive threads.
    plif_lane(x, out, tid, w);
    plif_lane(x, out, tid + NTHR, w);
}

extern "C" void kernel_launch(void* const* d_in, const int* in_sizes, int n_in,
                              void* d_out, int out_size)
{
    const float4* x  = (const float4*)d_in[0];
    const float*  wp = (const float*)d_in[1];
    float4* out = (float4*)d_out;

    plif_kernel<<<NBLK, TPB>>>(x, wp, out);
}